// round 14
// baseline (speedup 1.0000x reference)
#include <cuda_runtime.h>

// Problem constants (fixed by the reference):
//   S=3 symmetries, B=512 batches, N=1000 points, G=32 (G^3=32768 voxels)
//   GRID_MIN = -0.5 + 0.5/32 = -0.484375, scale = GRID/(2*GBOUND) = 32
#define S_SYM   3
#define B_BATCH 512
#define N_PTS   1000
#define G3      32768
#define SB_TOT  (S_SYM * B_BATCH)
#define GRID_MIN_F (-0.484375f)
#define NTHREADS 512
#define NWARPS   (NTHREADS / 32)
#define NEDGE    384     // 3 axes * 4 clamp combos * 32 positions

// Per-batch partial sums: [0..511]=plane, [512..1023]=quat. Plus ticket.
__device__ float g_partial[2 * B_BATCH];
__device__ unsigned int g_count;   // zero-initialized; reset by last block

__device__ __forceinline__ float fast_sqrt(float x) {
    float r;
    asm("sqrt.approx.f32 %0, %1;" : "=f"(r) : "f"(x));
    return r;
}
__device__ __forceinline__ float fast_rcp(float x) {
    float r;
    asm("rcp.approx.f32 %0, %1;" : "=f"(r) : "f"(x));
    return r;
}

// Classify voxel for (x,y,z); returns true if edge/corner (>=2 coords clamped)
// and then *sidx = smem edge-cache index; else *glin = linear voxel index.
__device__ __forceinline__ bool classify(float x, float y, float z,
                                         int* sidx, int* glin)
{
    float vx = fminf(fmaxf((x - GRID_MIN_F) * 32.0f, 0.0f), 31.0f);
    float vy = fminf(fmaxf((y - GRID_MIN_F) * 32.0f, 0.0f), 31.0f);
    float vz = fminf(fmaxf((z - GRID_MIN_F) * 32.0f, 0.0f), 31.0f);
    int ix = __float2int_rn(vx);   // round-half-even == jnp.round after clip
    int iy = __float2int_rn(vy);
    int iz = __float2int_rn(vz);
    bool cx = (ix * (31 - ix) == 0);
    bool cy = (iy * (31 - iy) == 0);
    bool cz = (iz * (31 - iz) == 0);
    if (((int)cx + (int)cy + (int)cz) >= 2) {
        int idx;
        if (!cx)      idx =       ((iy >> 4) * 2 + (iz >> 4)) * 32 + ix;
        else if (!cy) idx = 128 + ((ix >> 4) * 2 + (iz >> 4)) * 32 + iy;
        else          idx = 256 + ((ix >> 4) * 2 + (iy >> 4)) * 32 + iz;
        *sidx = idx;
        return true;
    }
    *glin = ix * 1024 + iy * 32 + iz;
    return false;
}

// Gather one voxel's {cp0,cp1,cp2,vol}: smem for edges, global otherwise.
__device__ __forceinline__ void gather(bool e, int si, int gl,
                                       const float4* __restrict__ s_edge,
                                       const float* __restrict__ cpb,
                                       const float* __restrict__ vb,
                                       float* c0, float* c1, float* c2, float* vm)
{
    if (e) {
        float4 cc = s_edge[si];
        *c0 = cc.x; *c1 = cc.y; *c2 = cc.z; *vm = cc.w;
    } else {
        const float* c = cpb + 3 * gl;
        *vm = __ldg(vb + gl);
        *c0 = __ldg(c + 0); *c1 = __ldg(c + 1); *c2 = __ldg(c + 2);
    }
}

__device__ __forceinline__ float dist(float x, float y, float z,
                                      float c0, float c1, float c2, float vm)
{
    float m  = 1.0f - vm;
    float dx = (x - c0) * m;
    float dy = (y - c1) * m;
    float dz = (z - c2) * m;
    return fast_sqrt(fmaxf(dx * dx + dy * dy + dz * dz, 1e-30f));
}

__global__ __launch_bounds__(NTHREADS, 4)   // cap 32 regs -> 2048 thr/SM
void sym_loss_kernel(const float* __restrict__ planes,
                     const float* __restrict__ quats,
                     const float* __restrict__ cps,
                     const float* __restrict__ pts,
                     const float* __restrict__ vol,
                     float* __restrict__ out)
{
    __shared__ float4 s_pts[N_PTS];            // padded to 16B for LDS.128
    __shared__ float4 s_edge[NEDGE];           // {cp0,cp1,cp2,vol} of edge voxels
    // Affine rows: s_mat[s*6 + 0..2] = plane reflect rows (w = translation),
    //              s_mat[s*6 + 3..5] = quat rotate rows (w = 0).
    __shared__ float4 s_mat[S_SYM * 6];
    __shared__ float  s_red[2 * NWARPS];
    __shared__ int    s_is_last;

    const int b = blockIdx.x;                  // one block per batch
    const float* cpb = cps + (size_t)b * (3 * G3);
    const float* vb  = vol + (size_t)b * G3;

    // Stage the 384 edge voxels (>=2 coords clamped to 0/31).
    // Layout: axis = i/128 (the FREE axis), combo = (i%128)/32, pos = i%32.
    if (threadIdx.x < NEDGE) {
        int i = threadIdx.x;
        int axis  = i >> 7;
        int combo = (i >> 5) & 3;
        int pos   = i & 31;
        int hi0 = (combo >> 1) * 31;
        int hi1 = (combo & 1) * 31;
        int ix, iy, iz;
        if (axis == 0)      { ix = pos; iy = hi0; iz = hi1; }
        else if (axis == 1) { ix = hi0; iy = pos; iz = hi1; }
        else                { ix = hi0; iy = hi1; iz = pos; }
        int lin = ix * 1024 + iy * 32 + iz;
        const float* c = cpb + 3 * lin;
        s_edge[i] = make_float4(__ldg(c), __ldg(c + 1), __ldg(c + 2), __ldg(vb + lin));
    }
    // Precompute affine transform matrices (one thread per symmetry).
    if (threadIdx.x >= NEDGE && threadIdx.x < NEDGE + S_SYM) {
        int s = threadIdx.x - NEDGE;
        float4 pl = reinterpret_cast<const float4*>(planes)[s * B_BATCH + b];
        float4 qq = reinterpret_cast<const float4*>(quats)[s * B_BATCH + b];

        // Plane reflect: p' = (I - 2 n n^T / D) p - (2 d / D) n, D = |n|^2+1e-8
        float D  = pl.x * pl.x + pl.y * pl.y + pl.z * pl.z + 1e-8f;
        float f  = 2.0f * fast_rcp(D);
        float fa = f * pl.x, fb = f * pl.y, fc = f * pl.z, fd = f * pl.w;
        s_mat[s * 6 + 0] = make_float4(1.0f - fa * pl.x, -fa * pl.y, -fa * pl.z, -fd * pl.x);
        s_mat[s * 6 + 1] = make_float4(-fb * pl.x, 1.0f - fb * pl.y, -fb * pl.z, -fd * pl.y);
        s_mat[s * 6 + 2] = make_float4(-fc * pl.x, -fc * pl.y, 1.0f - fc * pl.z, -fd * pl.z);

        // Quat rotate (unnormalized q=(w,x,y,z)): exact |q|^2-scaled rotation.
        float w = qq.x, x = qq.y, y = qq.z, z = qq.w;
        float ww = w * w, xx = x * x, yy = y * y, zz = z * z;
        float xy = x * y, xz = x * z, yz = y * z;
        float wx = w * x, wy = w * y, wz = w * z;
        s_mat[s * 6 + 3] = make_float4(ww + xx - yy - zz, 2.0f * (xy - wz), 2.0f * (xz + wy), 0.0f);
        s_mat[s * 6 + 4] = make_float4(2.0f * (xy + wz), ww - xx + yy - zz, 2.0f * (yz - wx), 0.0f);
        s_mat[s * 6 + 5] = make_float4(2.0f * (xz - wy), 2.0f * (yz + wx), ww - xx - yy + zz, 0.0f);
    }
    // Stage the batch's points once (shared across all 3 symmetries).
    {
        const float* pb = pts + (size_t)b * (3 * N_PTS);
        for (int i = threadIdx.x; i < N_PTS; i += NTHREADS)
            s_pts[i] = make_float4(pb[3 * i + 0], pb[3 * i + 1], pb[3 * i + 2], 0.0f);
    }
    __syncthreads();

    // Each thread owns TWO points: tid and tid+512 (duplicate w/ weight 0 if OOR).
    const int t = threadIdx.x;
    const bool has2 = (t + NTHREADS) < N_PTS;     // t < 488
    const float w1 = has2 ? 1.0f : 0.0f;
    float4 P0 = s_pts[t];
    float4 P1 = s_pts[has2 ? (t + NTHREADS) : t];

    float lp = 0.0f, lq = 0.0f;

    #pragma unroll
    for (int s = 0; s < S_SYM; s++) {
        // Stream each matrix row through once, applying to BOTH points.
        float4 r;
        r = s_mat[s * 6 + 0];
        float ax0 = fmaf(r.x, P0.x, fmaf(r.y, P0.y, fmaf(r.z, P0.z, r.w)));
        float ax1 = fmaf(r.x, P1.x, fmaf(r.y, P1.y, fmaf(r.z, P1.z, r.w)));
        r = s_mat[s * 6 + 1];
        float ay0 = fmaf(r.x, P0.x, fmaf(r.y, P0.y, fmaf(r.z, P0.z, r.w)));
        float ay1 = fmaf(r.x, P1.x, fmaf(r.y, P1.y, fmaf(r.z, P1.z, r.w)));
        r = s_mat[s * 6 + 2];
        float az0 = fmaf(r.x, P0.x, fmaf(r.y, P0.y, fmaf(r.z, P0.z, r.w)));
        float az1 = fmaf(r.x, P1.x, fmaf(r.y, P1.y, fmaf(r.z, P1.z, r.w)));
        r = s_mat[s * 6 + 3];
        float bx0 = fmaf(r.x, P0.x, fmaf(r.y, P0.y, r.z * P0.z));
        float bx1 = fmaf(r.x, P1.x, fmaf(r.y, P1.y, r.z * P1.z));
        r = s_mat[s * 6 + 4];
        float by0 = fmaf(r.x, P0.x, fmaf(r.y, P0.y, r.z * P0.z));
        float by1 = fmaf(r.x, P1.x, fmaf(r.y, P1.y, r.z * P1.z));
        r = s_mat[s * 6 + 5];
        float bz0 = fmaf(r.x, P0.x, fmaf(r.y, P0.y, r.z * P0.z));
        float bz1 = fmaf(r.x, P1.x, fmaf(r.y, P1.y, r.z * P1.z));

        // Classify all four transformed points.
        int siA0 = 0, glA0 = 0, siA1 = 0, glA1 = 0;
        int siB0 = 0, glB0 = 0, siB1 = 0, glB1 = 0;
        bool eA0 = classify(ax0, ay0, az0, &siA0, &glA0);
        bool eA1 = classify(ax1, ay1, az1, &siA1, &glA1);
        bool eB0 = classify(bx0, by0, bz0, &siB0, &glB0);
        bool eB1 = classify(bx1, by1, bz1, &siB1, &glB1);

        // Gather all four voxels (batched for MLP).
        float cA00, cA01, cA02, vA0, cA10, cA11, cA12, vA1;
        float cB00, cB01, cB02, vB0, cB10, cB11, cB12, vB1;
        gather(eA0, siA0, glA0, s_edge, cpb, vb, &cA00, &cA01, &cA02, &vA0);
        gather(eA1, siA1, glA1, s_edge, cpb, vb, &cA10, &cA11, &cA12, &vA1);
        gather(eB0, siB0, glB0, s_edge, cpb, vb, &cB00, &cB01, &cB02, &vB0);
        gather(eB1, siB1, glB1, s_edge, cpb, vb, &cB10, &cB11, &cB12, &vB1);

        lp += dist(ax0, ay0, az0, cA00, cA01, cA02, vA0);
        lp  = fmaf(w1, dist(ax1, ay1, az1, cA10, cA11, cA12, vA1), lp);
        lq += dist(bx0, by0, bz0, cB00, cB01, cB02, vB0);
        lq  = fmaf(w1, dist(bx1, by1, bz1, cB10, cB11, cB12, vB1), lq);
    }

    // Deterministic block reduction: warp shuffle then fixed-order smem sum.
    #pragma unroll
    for (int off = 16; off > 0; off >>= 1) {
        lp += __shfl_down_sync(0xffffffffu, lp, off);
        lq += __shfl_down_sync(0xffffffffu, lq, off);
    }
    const int lane = threadIdx.x & 31;
    const int wid  = threadIdx.x >> 5;
    if (lane == 0) { s_red[wid] = lp; s_red[NWARPS + wid] = lq; }
    __syncthreads();
    if (threadIdx.x == 0) {
        float a = 0.0f, c2s = 0.0f;
        #pragma unroll
        for (int i = 0; i < NWARPS; i++) { a += s_red[i]; c2s += s_red[NWARPS + i]; }
        g_partial[b] = a;
        g_partial[B_BATCH + b] = c2s;
        __threadfence();
        unsigned tk = atomicAdd(&g_count, 1u);
        s_is_last = (tk == B_BATCH - 1);
    }
    __syncthreads();

    // Last block performs the final reduction in a FIXED order (deterministic
    // regardless of which block finishes last).
    if (s_is_last) {
        float a = 0.0f, c2s = 0.0f;
        for (int i = threadIdx.x; i < B_BATCH; i += NTHREADS) {
            a   += g_partial[i];
            c2s += g_partial[B_BATCH + i];
        }
        #pragma unroll
        for (int off = 16; off > 0; off >>= 1) {
            a   += __shfl_down_sync(0xffffffffu, a,   off);
            c2s += __shfl_down_sync(0xffffffffu, c2s, off);
        }
        if (lane == 0) { s_red[wid] = a; s_red[NWARPS + wid] = c2s; }
        __syncthreads();
        if (threadIdx.x == 0) {
            float sa = 0.0f, sc = 0.0f;
            #pragma unroll
            for (int i = 0; i < NWARPS; i++) { sa += s_red[i]; sc += s_red[NWARPS + i]; }
            out[0] = sa * (1.0f / (float)SB_TOT);
            out[1] = sc * (1.0f / (float)SB_TOT);
            g_count = 0;   // reset for next graph replay
        }
    }
}

extern "C" void kernel_launch(void* const* d_in, const int* in_sizes, int n_in,
                              void* d_out, int out_size)
{
    const float* planes = (const float*)d_in[0];  // (3,512,4)
    const float* quats  = (const float*)d_in[1];  // (3,512,4)
    const float* cps    = (const float*)d_in[2];  // (512, 32768*3)
    const float* pts    = (const float*)d_in[3];  // (512,1000,3)
    const float* vol    = (const float*)d_in[4];  // (512,1,32,32,32)
    float* out = (float*)d_out;                   // [lp_mean, lq_mean]

    sym_loss_kernel<<<B_BATCH, NTHREADS>>>(planes, quats, cps, pts, vol, out);
}

// round 15
// speedup vs baseline: 1.0817x; 1.0817x over previous
#include <cuda_runtime.h>

// Problem constants (fixed by the reference):
//   S=3 symmetries, B=512 batches, N=1000 points, G=32 (G^3=32768 voxels)
//   GRID_MIN = -0.5 + 0.5/32 = -0.484375, scale = GRID/(2*GBOUND) = 32
#define S_SYM   3
#define B_BATCH 512
#define N_PTS   1000
#define G3      32768
#define SB_TOT  (S_SYM * B_BATCH)
#define GRID_MIN_F (-0.484375f)
#define NTHREADS 512
#define NWARPS   (NTHREADS / 32)
#define NEDGE    384     // 3 axes * 4 clamp combos * 32 positions

// Per-batch partial sums: [0..511]=plane, [512..1023]=quat. Plus ticket.
__device__ float g_partial[2 * B_BATCH];
__device__ unsigned int g_count;   // zero-initialized; reset by last block

__device__ __forceinline__ float fast_sqrt(float x) {
    float r;
    asm("sqrt.approx.f32 %0, %1;" : "=f"(r) : "f"(x));
    return r;
}
__device__ __forceinline__ float fast_rcp(float x) {
    float r;
    asm("rcp.approx.f32 %0, %1;" : "=f"(r) : "f"(x));
    return r;
}

// Classify voxel for (x,y,z). ALWAYS writes a valid smem edge index to *sidx
// (in [0,384) even for interior voxels) and the voxel linear index to *glin.
// Returns true if the voxel is an edge/corner (>=2 coords clamped).
__device__ __forceinline__ bool classify(float x, float y, float z,
                                         int* sidx, int* glin)
{
    float vx = fminf(fmaxf((x - GRID_MIN_F) * 32.0f, 0.0f), 31.0f);
    float vy = fminf(fmaxf((y - GRID_MIN_F) * 32.0f, 0.0f), 31.0f);
    float vz = fminf(fmaxf((z - GRID_MIN_F) * 32.0f, 0.0f), 31.0f);
    int ix = __float2int_rn(vx);   // round-half-even == jnp.round after clip
    int iy = __float2int_rn(vy);
    int iz = __float2int_rn(vz);
    bool cx = (ix * (31 - ix) == 0);
    bool cy = (iy * (31 - iy) == 0);
    bool cz = (iz * (31 - iz) == 0);
    int idx;
    if (!cx)      idx =       ((iy >> 4) * 2 + (iz >> 4)) * 32 + ix;
    else if (!cy) idx = 128 + ((ix >> 4) * 2 + (iz >> 4)) * 32 + iy;
    else          idx = 256 + ((ix >> 4) * 2 + (iy >> 4)) * 32 + iz;
    *sidx = idx;
    *glin = ix * 1024 + iy * 32 + iz;
    return ((int)cx + (int)cy + (int)cz) >= 2;
}

// Branchless gather: always read the (always-valid) smem slot, then override
// with predicated global loads when the voxel is interior. No BSSY/BSYNC.
__device__ __forceinline__ void gather(bool e, int si, int gl,
                                       const float4* __restrict__ s_edge,
                                       const float* __restrict__ cpb,
                                       const float* __restrict__ vb,
                                       float* c0, float* c1, float* c2, float* vm)
{
    float4 cc = s_edge[si];
    float a0 = cc.x, a1 = cc.y, a2 = cc.z, a3 = cc.w;
    if (!e) {
        const float* c = cpb + 3 * gl;
        a3 = __ldg(vb + gl);
        a0 = __ldg(c + 0);
        a1 = __ldg(c + 1);
        a2 = __ldg(c + 2);
    }
    *c0 = a0; *c1 = a1; *c2 = a2; *vm = a3;
}

__global__ __launch_bounds__(NTHREADS, 4)   // cap 32 regs -> 2048 thr/SM
void sym_loss_kernel(const float* __restrict__ planes,
                     const float* __restrict__ quats,
                     const float* __restrict__ cps,
                     const float* __restrict__ pts,
                     const float* __restrict__ vol,
                     float* __restrict__ out)
{
    __shared__ float4 s_pts[N_PTS];            // padded to 16B for LDS.128
    __shared__ float4 s_edge[NEDGE];           // {cp0,cp1,cp2,vol} of edge voxels
    // Affine rows: s_mat[s*6 + 0..2] = plane reflect rows (w = translation),
    //              s_mat[s*6 + 3..5] = quat rotate rows (w = 0).
    __shared__ float4 s_mat[S_SYM * 6];
    __shared__ float  s_red[2 * NWARPS];
    __shared__ int    s_is_last;

    const int b = blockIdx.x;                  // one block per batch
    const float* cpb = cps + (size_t)b * (3 * G3);
    const float* vb  = vol + (size_t)b * G3;

    // Stage the 384 edge voxels (>=2 coords clamped to 0/31).
    // Layout: axis = i/128 (the FREE axis), combo = (i%128)/32, pos = i%32.
    if (threadIdx.x < NEDGE) {
        int i = threadIdx.x;
        int axis  = i >> 7;
        int combo = (i >> 5) & 3;
        int pos   = i & 31;
        int hi0 = (combo >> 1) * 31;
        int hi1 = (combo & 1) * 31;
        int ix, iy, iz;
        if (axis == 0)      { ix = pos; iy = hi0; iz = hi1; }
        else if (axis == 1) { ix = hi0; iy = pos; iz = hi1; }
        else                { ix = hi0; iy = hi1; iz = pos; }
        int lin = ix * 1024 + iy * 32 + iz;
        const float* c = cpb + 3 * lin;
        s_edge[i] = make_float4(__ldg(c), __ldg(c + 1), __ldg(c + 2), __ldg(vb + lin));
    }
    // Precompute affine transform matrices (one thread per symmetry).
    if (threadIdx.x >= NEDGE && threadIdx.x < NEDGE + S_SYM) {
        int s = threadIdx.x - NEDGE;
        float4 pl = reinterpret_cast<const float4*>(planes)[s * B_BATCH + b];
        float4 qq = reinterpret_cast<const float4*>(quats)[s * B_BATCH + b];

        // Plane reflect: p' = (I - 2 n n^T / D) p - (2 d / D) n, D = |n|^2+1e-8
        float D  = pl.x * pl.x + pl.y * pl.y + pl.z * pl.z + 1e-8f;
        float f  = 2.0f * fast_rcp(D);
        float fa = f * pl.x, fb = f * pl.y, fc = f * pl.z, fd = f * pl.w;
        s_mat[s * 6 + 0] = make_float4(1.0f - fa * pl.x, -fa * pl.y, -fa * pl.z, -fd * pl.x);
        s_mat[s * 6 + 1] = make_float4(-fb * pl.x, 1.0f - fb * pl.y, -fb * pl.z, -fd * pl.y);
        s_mat[s * 6 + 2] = make_float4(-fc * pl.x, -fc * pl.y, 1.0f - fc * pl.z, -fd * pl.z);

        // Quat rotate (unnormalized q=(w,x,y,z)): exact |q|^2-scaled rotation.
        float w = qq.x, x = qq.y, y = qq.z, z = qq.w;
        float ww = w * w, xx = x * x, yy = y * y, zz = z * z;
        float xy = x * y, xz = x * z, yz = y * z;
        float wx = w * x, wy = w * y, wz = w * z;
        s_mat[s * 6 + 3] = make_float4(ww + xx - yy - zz, 2.0f * (xy - wz), 2.0f * (xz + wy), 0.0f);
        s_mat[s * 6 + 4] = make_float4(2.0f * (xy + wz), ww - xx + yy - zz, 2.0f * (yz - wx), 0.0f);
        s_mat[s * 6 + 5] = make_float4(2.0f * (xz - wy), 2.0f * (yz + wx), ww - xx - yy + zz, 0.0f);
    }
    // Stage the batch's points once (shared across all 3 symmetries).
    {
        const float* pb = pts + (size_t)b * (3 * N_PTS);
        for (int i = threadIdx.x; i < N_PTS; i += NTHREADS)
            s_pts[i] = make_float4(pb[3 * i + 0], pb[3 * i + 1], pb[3 * i + 2], 0.0f);
    }
    __syncthreads();

    float lp = 0.0f, lq = 0.0f;

    for (int n = threadIdx.x; n < N_PTS; n += NTHREADS) {
        float4 p = s_pts[n];
        const float px = p.x, py = p.y, pz = p.z;

        #pragma unroll
        for (int s = 0; s < S_SYM; s++) {
            // plane reflect: 9 FMA
            float4 r0 = s_mat[s * 6 + 0];
            float4 r1 = s_mat[s * 6 + 1];
            float4 r2 = s_mat[s * 6 + 2];
            float tx0 = fmaf(r0.x, px, fmaf(r0.y, py, fmaf(r0.z, pz, r0.w)));
            float ty0 = fmaf(r1.x, px, fmaf(r1.y, py, fmaf(r1.z, pz, r1.w)));
            float tz0 = fmaf(r2.x, px, fmaf(r2.y, py, fmaf(r2.z, pz, r2.w)));

            // quat rotate: 9 FMA
            float4 u0 = s_mat[s * 6 + 3];
            float4 u1 = s_mat[s * 6 + 4];
            float4 u2 = s_mat[s * 6 + 5];
            float tx1 = fmaf(u0.x, px, fmaf(u0.y, py, u0.z * pz));
            float ty1 = fmaf(u1.x, px, fmaf(u1.y, py, u1.z * pz));
            float tz1 = fmaf(u2.x, px, fmaf(u2.y, py, u2.z * pz));

            int si0 = 0, gl0 = 0, si1 = 0, gl1 = 0;
            bool e0 = classify(tx0, ty0, tz0, &si0, &gl0);
            bool e1 = classify(tx1, ty1, tz1, &si1, &gl1);

            // Branchless gathers (predicated LDG override of smem read).
            float vm0, c00, c01, c02, vm1, c10, c11, c12;
            gather(e0, si0, gl0, s_edge, cpb, vb, &c00, &c01, &c02, &vm0);
            gather(e1, si1, gl1, s_edge, cpb, vb, &c10, &c11, &c12, &vm1);

            float m0 = 1.0f - vm0;
            float dx = (tx0 - c00) * m0;
            float dy = (ty0 - c01) * m0;
            float dz = (tz0 - c02) * m0;
            lp += fast_sqrt(fmaxf(dx * dx + dy * dy + dz * dz, 1e-30f));

            float m1 = 1.0f - vm1;
            float ex = (tx1 - c10) * m1;
            float ey = (ty1 - c11) * m1;
            float ez = (tz1 - c12) * m1;
            lq += fast_sqrt(fmaxf(ex * ex + ey * ey + ez * ez, 1e-30f));
        }
    }

    // Deterministic block reduction: warp shuffle then fixed-order smem sum.
    #pragma unroll
    for (int off = 16; off > 0; off >>= 1) {
        lp += __shfl_down_sync(0xffffffffu, lp, off);
        lq += __shfl_down_sync(0xffffffffu, lq, off);
    }
    const int lane = threadIdx.x & 31;
    const int wid  = threadIdx.x >> 5;
    if (lane == 0) { s_red[wid] = lp; s_red[NWARPS + wid] = lq; }
    __syncthreads();
    if (threadIdx.x == 0) {
        float a = 0.0f, c2s = 0.0f;
        #pragma unroll
        for (int i = 0; i < NWARPS; i++) { a += s_red[i]; c2s += s_red[NWARPS + i]; }
        g_partial[b] = a;
        g_partial[B_BATCH + b] = c2s;
        __threadfence();
        unsigned t = atomicAdd(&g_count, 1u);
        s_is_last = (t == B_BATCH - 1);
    }
    __syncthreads();

    // Last block performs the final reduction in a FIXED order (deterministic
    // regardless of which block finishes last).
    if (s_is_last) {
        float a = 0.0f, c2s = 0.0f;
        for (int i = threadIdx.x; i < B_BATCH; i += NTHREADS) {
            a   += g_partial[i];
            c2s += g_partial[B_BATCH + i];
        }
        #pragma unroll
        for (int off = 16; off > 0; off >>= 1) {
            a   += __shfl_down_sync(0xffffffffu, a,   off);
            c2s += __shfl_down_sync(0xffffffffu, c2s, off);
        }
        if (lane == 0) { s_red[wid] = a; s_red[NWARPS + wid] = c2s; }
        __syncthreads();
        if (threadIdx.x == 0) {
            float sa = 0.0f, sc = 0.0f;
            #pragma unroll
            for (int i = 0; i < NWARPS; i++) { sa += s_red[i]; sc += s_red[NWARPS + i]; }
            out[0] = sa * (1.0f / (float)SB_TOT);
            out[1] = sc * (1.0f / (float)SB_TOT);
            g_count = 0;   // reset for next graph replay
        }
    }
}

extern "C" void kernel_launch(void* const* d_in, const int* in_sizes, int n_in,
                              void* d_out, int out_size)
{
    const float* planes = (const float*)d_in[0];  // (3,512,4)
    const float* quats  = (const float*)d_in[1];  // (3,512,4)
    const float* cps    = (const float*)d_in[2];  // (512, 32768*3)
    const float* pts    = (const float*)d_in[3];  // (512,1000,3)
    const float* vol    = (const float*)d_in[4];  // (512,1,32,32,32)
    float* out = (float*)d_out;                   // [lp_mean, lq_mean]

    sym_loss_kernel<<<B_BATCH, NTHREADS>>>(planes, quats, cps, pts, vol, out);
}